// round 4
// baseline (speedup 1.0000x reference)
#include <cuda_runtime.h>
#include <cuda_bf16.h>
#include <math.h>
#include <stdint.h>

// ---------------------------------------------------------------------------
// QuantumTSTransformer: 12-qubit statevector sim.
//   B=64 batches, T=32 timesteps, DEGREE=4, sim14 ansatz 2 layers (96 rots),
//   qff readout layer (48 rots), DIM=4096.
// Strategy: one CTA per circuit group; state lives in smem (32KB), gates applied
// in 8 "phases" per layer where 4 qubits are register-resident (16 complex amps
// per thread, 256 threads). XOR swizzle on smem index avoids bank conflicts.
// ---------------------------------------------------------------------------

#define NQ       12
#define DIM      4096
#define BATCH    64
#define TSTEPS   32
#define NROTS    96
#define QFFROTS  48
#define DEGREE   4
#define FDIM     64
#define ODIM     8
#define TGROUP   4                     // t-values per CTA in circuit kernel
#define NBLK_CIRC (BATCH * (TSTEPS / TGROUP))   // 512

// Scratch (device globals: no allocation allowed)
__device__ float2 g_work[DEGREE + 1][BATCH * DIM];   // work_0=base, work_1..4
__device__ float2 g_cs[BATCH * TSTEPS * NROTS];      // (cos(h), sin(h)) per rot
__device__ float2 g_csqff[QFFROTS];

// smem slot swizzle: bijective, conflict-free for all phase patterns
__device__ __forceinline__ uint32_t sw(uint32_t i) { return i ^ ((i >> 4) & 0xFu); }

// base address: deposit 8 tid bits into the amplitude-index bits NOT in {P0..P3}
template<int P0, int P1, int P2, int P3>
__device__ __forceinline__ uint32_t phase_base(int tid) {
    constexpr uint32_t M = (1u << P0) | (1u << P1) | (1u << P2) | (1u << P3);
    uint32_t base = 0;
    int tb = 0;
#pragma unroll
    for (int pos = 0; pos < NQ; ++pos) {
        if (!((M >> pos) & 1u)) {
            base |= ((uint32_t)(tid >> tb) & 1u) << pos;
            ++tb;
        }
    }
    return base;
}

template<int P0, int P1, int P2, int P3>
__device__ __forceinline__ uint32_t pidx(uint32_t base, int j) {
    return base
        | ((j & 1) ? (1u << P0) : 0u)
        | ((j & 2) ? (1u << P1) : 0u)
        | ((j & 4) ? (1u << P2) : 0u)
        | ((j & 8) ? (1u << P3) : 0u);
}

// RY on register-bit RB:  a0' = c a0 - s a1 ; a1' = s a0 + c a1
template<int RB>
__device__ __forceinline__ void gry(float2* r, float2 cs) {
    const float c = cs.x, s = cs.y;
#pragma unroll
    for (int j = 0; j < 16; ++j) {
        if (!(j & (1 << RB))) {
            float2 a0 = r[j], a1 = r[j | (1 << RB)];
            r[j].x = c * a0.x - s * a1.x;
            r[j].y = c * a0.y - s * a1.y;
            r[j | (1 << RB)].x = s * a0.x + c * a1.x;
            r[j | (1 << RB)].y = s * a0.y + c * a1.y;
        }
    }
}

// CRX: control register-bit RBC == 1, target RBT.
//   a0' = c a0 - i s a1 ; a1' = c a1 - i s a0
template<int RBC, int RBT>
__device__ __forceinline__ void gcrx(float2* r, float2 cs) {
    const float c = cs.x, s = cs.y;
#pragma unroll
    for (int j = 0; j < 16; ++j) {
        if ((j & (1 << RBC)) && !(j & (1 << RBT))) {
            float2 a0 = r[j], a1 = r[j | (1 << RBT)];
            r[j].x = c * a0.x + s * a1.y;
            r[j].y = c * a0.y - s * a1.x;
            r[j | (1 << RBT)].x = c * a1.x + s * a0.y;
            r[j | (1 << RBT)].y = c * a1.y - s * a0.x;
        }
    }
}

#define PHASE_LOAD(P0,P1,P2,P3)                                            \
    uint32_t base = phase_base<P0,P1,P2,P3>(tid);                          \
    float2 r[16];                                                          \
    _Pragma("unroll")                                                      \
    for (int j = 0; j < 16; ++j) r[j] = st[sw(pidx<P0,P1,P2,P3>(base, j))];

#define PHASE_STORE(P0,P1,P2,P3)                                           \
    _Pragma("unroll")                                                      \
    for (int j = 0; j < 16; ++j) st[sw(pidx<P0,P1,P2,P3>(base, j))] = r[j];

// ---- the 8 phases of one sim14 layer (wire w <-> amplitude bit 11-w) ----
// Layer = RY ring (idx 0..11) fused with chainA (idx 12..23), then RY ring
// (24..35) fused with chainB (36..47). Groupings preserve gate ordering.

__device__ __forceinline__ void phA1(float2* st, const float2* c, int tid) {
    // wires {0,11,10,9} -> bits {11,0,1,2}
    PHASE_LOAD(11, 0, 1, 2);
    gry<0>(r, c[0]);  gry<1>(r, c[11]); gry<2>(r, c[10]); gry<3>(r, c[9]);
    gcrx<1, 0>(r, c[12]);   // CRX(11->0)
    gcrx<2, 1>(r, c[13]);   // CRX(10->11)
    gcrx<3, 2>(r, c[14]);   // CRX(9->10)
    PHASE_STORE(11, 0, 1, 2);
}
__device__ __forceinline__ void phA2(float2* st, const float2* c, int tid) {
    // wires {9,8,7,6} -> bits {2,3,4,5}
    PHASE_LOAD(2, 3, 4, 5);
    gry<1>(r, c[8]); gry<2>(r, c[7]); gry<3>(r, c[6]);
    gcrx<1, 0>(r, c[15]);   // CRX(8->9)
    gcrx<2, 1>(r, c[16]);   // CRX(7->8)
    gcrx<3, 2>(r, c[17]);   // CRX(6->7)
    PHASE_STORE(2, 3, 4, 5);
}
__device__ __forceinline__ void phA3(float2* st, const float2* c, int tid) {
    // wires {6,5,4,3} -> bits {5,6,7,8}
    PHASE_LOAD(5, 6, 7, 8);
    gry<1>(r, c[5]); gry<2>(r, c[4]); gry<3>(r, c[3]);
    gcrx<1, 0>(r, c[18]);   // CRX(5->6)
    gcrx<2, 1>(r, c[19]);   // CRX(4->5)
    gcrx<3, 2>(r, c[20]);   // CRX(3->4)
    PHASE_STORE(5, 6, 7, 8);
}
__device__ __forceinline__ void phA4(float2* st, const float2* c, int tid) {
    // wires {3,2,1,0} -> bits {8,9,10,11}
    PHASE_LOAD(8, 9, 10, 11);
    gry<1>(r, c[2]); gry<2>(r, c[1]);
    gcrx<1, 0>(r, c[21]);   // CRX(2->3)
    gcrx<2, 1>(r, c[22]);   // CRX(1->2)
    gcrx<3, 2>(r, c[23]);   // CRX(0->1)
    PHASE_STORE(8, 9, 10, 11);
}
__device__ __forceinline__ void phB1(float2* st, const float2* c, int tid) {
    // wires {10,11,0,1} -> bits {1,0,11,10}
    PHASE_LOAD(1, 0, 11, 10);
    gry<0>(r, c[34]); gry<1>(r, c[35]); gry<2>(r, c[24]); gry<3>(r, c[25]);
    gcrx<1, 0>(r, c[36]);   // CRX(11->10)
    gcrx<2, 1>(r, c[37]);   // CRX(0->11)
    gcrx<3, 2>(r, c[38]);   // CRX(1->0)
    PHASE_STORE(1, 0, 11, 10);
}
__device__ __forceinline__ void phB2(float2* st, const float2* c, int tid) {
    // wires {1,2,3,4} -> bits {10,9,8,7}
    PHASE_LOAD(10, 9, 8, 7);
    gry<1>(r, c[26]); gry<2>(r, c[27]); gry<3>(r, c[28]);
    gcrx<1, 0>(r, c[39]);   // CRX(2->1)
    gcrx<2, 1>(r, c[40]);   // CRX(3->2)
    gcrx<3, 2>(r, c[41]);   // CRX(4->3)
    PHASE_STORE(10, 9, 8, 7);
}
__device__ __forceinline__ void phB3(float2* st, const float2* c, int tid) {
    // wires {4,5,6,7} -> bits {7,6,5,4}
    PHASE_LOAD(7, 6, 5, 4);
    gry<1>(r, c[29]); gry<2>(r, c[30]); gry<3>(r, c[31]);
    gcrx<1, 0>(r, c[42]);   // CRX(5->4)
    gcrx<2, 1>(r, c[43]);   // CRX(6->5)
    gcrx<3, 2>(r, c[44]);   // CRX(7->6)
    PHASE_STORE(7, 6, 5, 4);
}
__device__ __forceinline__ void phB4(float2* st, const float2* c, int tid) {
    // wires {7,8,9,10} -> bits {4,3,2,1}
    PHASE_LOAD(4, 3, 2, 1);
    gry<1>(r, c[32]); gry<2>(r, c[33]);
    gcrx<1, 0>(r, c[45]);   // CRX(8->7)
    gcrx<2, 1>(r, c[46]);   // CRX(9->8)
    gcrx<3, 2>(r, c[47]);   // CRX(10->9)
    PHASE_STORE(4, 3, 2, 1);
}

__device__ __forceinline__ void run_layer(float2* st, const float2* c, int tid) {
    phA1(st, c, tid); __syncthreads();
    phA2(st, c, tid); __syncthreads();
    phA3(st, c, tid); __syncthreads();
    phA4(st, c, tid); __syncthreads();
    phB1(st, c, tid); __syncthreads();
    phB2(st, c, tid); __syncthreads();
    phB3(st, c, tid); __syncthreads();
    phB4(st, c, tid); __syncthreads();
}

// ---------------------------------------------------------------------------
// Kernel 1: params. theta = sigmoid(x@W^T + b) * 2pi ; store (cos, sin)(theta/2)
// ---------------------------------------------------------------------------
__global__ void param_kernel(const float* __restrict__ x,
                             const float* __restrict__ Wp,
                             const float* __restrict__ bp,
                             const float* __restrict__ qff) {
    __shared__ float xr[FDIM];
    int bt = blockIdx.x;            // 0..2047
    int r = threadIdx.x;            // 0..95
    if (r < FDIM) xr[r] = x[bt * FDIM + r];
    __syncthreads();
    float acc = bp[r];
#pragma unroll
    for (int f = 0; f < FDIM; ++f) acc += xr[f] * Wp[r * FDIM + f];
    float sg = 1.0f / (1.0f + expf(-acc));
    float h = 3.14159265358979323846f * sg;   // theta/2 = pi * sigmoid
    g_cs[bt * NROTS + r] = make_float2(cosf(h), sinf(h));
    if (bt == 0 && r < QFFROTS) {
        float hq = 0.5f * qff[r];
        g_csqff[r] = make_float2(cosf(hq), sinf(hq));
    }
}

// ---------------------------------------------------------------------------
// Kernel 2: zero scratch, set work_0 = |0...0> per batch
// ---------------------------------------------------------------------------
__global__ void init_kernel() {
    uint32_t e = blockIdx.x * blockDim.x + threadIdx.x;   // 0 .. 5*64*4096-1
    float2* flat = &g_work[0][0];
    uint32_t buf = e >> 18;                 // /262144
    uint32_t rem = e & 0x3FFFFu;
    float2 v = make_float2(0.f, 0.f);
    if (buf == 0 && (rem & (DIM - 1)) == 0) v.x = 1.f;
    flat[e] = v;
}

// ---------------------------------------------------------------------------
// Kernel 3: one polynomial degree.
// grid = 512 (b * 8 tgroups), each CTA runs TGROUP circuits and accumulates
// mix[t]*psi in registers, then RED.global into work_out.
// ---------------------------------------------------------------------------
__global__ void __launch_bounds__(256, 2)
circuit_kernel(const float2* __restrict__ win, float2* __restrict__ wout,
               const float* __restrict__ mix_re, const float* __restrict__ mix_im) {
    __shared__ float2 st[DIM];
    const int tid = threadIdx.x;
    const int b = blockIdx.x >> 3;
    const int tg = blockIdx.x & 7;

    float2 A[16];
#pragma unroll
    for (int j = 0; j < 16; ++j) A[j] = make_float2(0.f, 0.f);

    for (int tt = 0; tt < TGROUP; ++tt) {
        const int t = tg * TGROUP + tt;
        __syncthreads();                      // prior iter readers done
#pragma unroll
        for (int k = 0; k < 16; ++k) {
            int i = tid + 256 * k;
            st[sw((uint32_t)i)] = win[b * DIM + i];
        }
        __syncthreads();

        const float2* c0 = &g_cs[(b * TSTEPS + t) * NROTS];
        run_layer(st, c0, tid);               // layer 0 (8 phases)
        const float2* c1 = c0 + 48;
        // layer 1: first 7 phases, last phase kept in registers
        phA1(st, c1, tid); __syncthreads();
        phA2(st, c1, tid); __syncthreads();
        phA3(st, c1, tid); __syncthreads();
        phA4(st, c1, tid); __syncthreads();
        phB1(st, c1, tid); __syncthreads();
        phB2(st, c1, tid); __syncthreads();
        phB3(st, c1, tid); __syncthreads();
        {   // phB4 without store: accumulate mix[t] * psi
            PHASE_LOAD(4, 3, 2, 1);
            gry<1>(r, c1[32]); gry<2>(r, c1[33]);
            gcrx<1, 0>(r, c1[45]);
            gcrx<2, 1>(r, c1[46]);
            gcrx<3, 2>(r, c1[47]);
            const float mr = mix_re[t], mi = mix_im[t];
#pragma unroll
            for (int j = 0; j < 16; ++j) {
                A[j].x += mr * r[j].x - mi * r[j].y;
                A[j].y += mr * r[j].y + mi * r[j].x;
            }
        }
    }
    // flush accumulator (B4 amplitude mapping)
    uint32_t base = phase_base<4, 3, 2, 1>(tid);
#pragma unroll
    for (int j = 0; j < 16; ++j) {
        uint32_t i = pidx<4, 3, 2, 1>(base, j);
        atomicAdd(&wout[b * DIM + i].x, A[j].x);
        atomicAdd(&wout[b * DIM + i].y, A[j].y);
    }
}

// ---------------------------------------------------------------------------
// Kernel 4: assemble acc, normalize, qff layer, Pauli expvals, output linear.
// grid = 64 (one CTA per batch), 256 threads.
// ---------------------------------------------------------------------------
__global__ void final_kernel(const float* __restrict__ poly,
                             const float* __restrict__ W_out,
                             const float* __restrict__ b_out,
                             float* __restrict__ out) {
    __shared__ float2 st[DIM];
    __shared__ float red[37];            // [0..35] expvals, [36] sumsq
    const int tid = threadIdx.x;
    const int b = blockIdx.x;

    float p[DEGREE + 1];
#pragma unroll
    for (int d = 0; d <= DEGREE; ++d) p[d] = poly[d];
    float sabs = 0.f;
#pragma unroll
    for (int d = 0; d <= DEGREE; ++d) sabs += fabsf(p[d]);
    const float inv_s = 1.f / sabs;

    if (tid == 0) red[36] = 0.f;
    float lsq = 0.f;
#pragma unroll
    for (int k = 0; k < 16; ++k) {
        int i = tid + 256 * k;
        float2 v = make_float2(0.f, 0.f);
#pragma unroll
        for (int d = 0; d <= DEGREE; ++d) {
            float2 w = g_work[d][b * DIM + i];
            v.x += p[d] * w.x;
            v.y += p[d] * w.y;
        }
        v.x *= inv_s; v.y *= inv_s;
        st[sw((uint32_t)i)] = v;
        lsq += v.x * v.x + v.y * v.y;
    }
#pragma unroll
    for (int o = 16; o > 0; o >>= 1) lsq += __shfl_xor_sync(0xffffffffu, lsq, o);
    if ((tid & 31) == 0) atomicAdd(&red[36], lsq);
    __syncthreads();

    const float f = 1.f / (sqrtf(red[36]) + 1e-9f);
#pragma unroll
    for (int k = 0; k < 16; ++k) {
        int i = tid + 256 * k;
        uint32_t s_ = sw((uint32_t)i);
        float2 v = st[s_];
        v.x *= f; v.y *= f;
        st[s_] = v;
    }
    __syncthreads();

    run_layer(st, g_csqff, tid);     // qff: one sim14 layer

    if (tid < 36) red[tid] = 0.f;
    __syncthreads();

    float xx[NQ], yy[NQ], zz[NQ];
#pragma unroll
    for (int w = 0; w < NQ; ++w) { xx[w] = 0.f; yy[w] = 0.f; zz[w] = 0.f; }

#pragma unroll
    for (int k = 0; k < 16; ++k) {
        int i = tid + 256 * k;
        float2 a = st[sw((uint32_t)i)];
        float n2 = a.x * a.x + a.y * a.y;
#pragma unroll
        for (int w = 0; w < NQ; ++w) {
            int pbit = 11 - w;
            if (((i >> pbit) & 1) == 0) {
                float2 a1 = st[sw((uint32_t)(i | (1 << pbit)))];
                xx[w] += 2.f * (a.x * a1.x + a.y * a1.y);
                yy[w] += 2.f * (a.x * a1.y - a.y * a1.x);
                zz[w] += n2;
            } else {
                zz[w] -= n2;
            }
        }
    }
#pragma unroll
    for (int w = 0; w < NQ; ++w) {
        atomicAdd(&red[w], xx[w]);
        atomicAdd(&red[12 + w], yy[w]);
        atomicAdd(&red[24 + w], zz[w]);
    }
    __syncthreads();

    if (tid < ODIM) {
        float acc = b_out[tid];
#pragma unroll
        for (int j = 0; j < 36; ++j) acc += W_out[tid * 36 + j] * red[j];
        out[b * ODIM + tid] = acc;
    }
}

// ---------------------------------------------------------------------------
// Inputs (metadata order): x, W_proj, b_proj, poly_coeffs, mix_re, mix_im,
//                          qff_params, W_out, b_out.  Output: float32 [64,8].
// ---------------------------------------------------------------------------
extern "C" void kernel_launch(void* const* d_in, const int* in_sizes, int n_in,
                              void* d_out, int out_size) {
    (void)in_sizes; (void)n_in; (void)out_size;
    const float* x      = (const float*)d_in[0];
    const float* W_proj = (const float*)d_in[1];
    const float* b_proj = (const float*)d_in[2];
    const float* poly   = (const float*)d_in[3];
    const float* mix_re = (const float*)d_in[4];
    const float* mix_im = (const float*)d_in[5];
    const float* qff    = (const float*)d_in[6];
    const float* W_out  = (const float*)d_in[7];
    const float* b_out  = (const float*)d_in[8];
    float* out = (float*)d_out;

    param_kernel<<<BATCH * TSTEPS, NROTS>>>(x, W_proj, b_proj, qff);
    init_kernel<<<(DEGREE + 1) * BATCH * DIM / 256, 256>>>();

    float2* w0; float2* w1; float2* w2; float2* w3; float2* w4;
    cudaGetSymbolAddress((void**)&w0, g_work);   // base of g_work
    w1 = w0 + 1 * BATCH * DIM;
    w2 = w0 + 2 * BATCH * DIM;
    w3 = w0 + 3 * BATCH * DIM;
    w4 = w0 + 4 * BATCH * DIM;

    circuit_kernel<<<NBLK_CIRC, 256>>>(w0, w1, mix_re, mix_im);
    circuit_kernel<<<NBLK_CIRC, 256>>>(w1, w2, mix_re, mix_im);
    circuit_kernel<<<NBLK_CIRC, 256>>>(w2, w3, mix_re, mix_im);
    circuit_kernel<<<NBLK_CIRC, 256>>>(w3, w4, mix_re, mix_im);

    final_kernel<<<BATCH, 256>>>(poly, W_out, b_out, out);
}

// round 5
// speedup vs baseline: 1.0241x; 1.0241x over previous
#include <cuda_runtime.h>
#include <cuda_bf16.h>
#include <math.h>
#include <stdint.h>

// ---------------------------------------------------------------------------
// QuantumTSTransformer: 12-qubit statevector sim, packed f32x2 arithmetic.
//   B=64, T=32, DEGREE=4, sim14 2 layers (96 rots), qff layer (48), DIM=4096.
// One CTA per (b, t-pair); state in smem (32KB) as packed (re,im) b64 words;
// gates in 8 phases/layer with 4 register-resident qubits (16 packed amps /
// thread, 256 threads). All gate math uses fma.rn.f32x2 / mul.rn.f32x2.
// ---------------------------------------------------------------------------

#define NQ       12
#define DIM      4096
#define BATCH    64
#define TSTEPS   32
#define NROTS    96
#define QFFROTS  48
#define DEGREE   4
#define FDIM     64
#define ODIM     8
#define TGROUP   2                     // t-values per CTA in circuit kernel
#define NBLK_CIRC (BATCH * (TSTEPS / TGROUP))   // 1024

typedef unsigned long long ull;

// Scratch (device globals: no allocation allowed)
__device__ float2 g_work[DEGREE + 1][BATCH * DIM];   // work_0=base, work_1..4
__device__ float2 g_cs[BATCH * TSTEPS * NROTS];      // (cos(h), sin(h)) per rot
__device__ float2 g_csqff[QFFROTS];

// ---------------- packed f32x2 helpers ----------------
__device__ __forceinline__ ull pk2(float x, float y) {
    ull r; asm("mov.b64 %0, {%1, %2};" : "=l"(r) : "f"(x), "f"(y)); return r;
}
__device__ __forceinline__ ull dup2(float x) { return pk2(x, x); }
__device__ __forceinline__ float2 upk(ull v) {
    float2 r; asm("mov.b64 {%0, %1}, %2;" : "=f"(r.x), "=f"(r.y) : "l"(v)); return r;
}
__device__ __forceinline__ ull swp(ull v) {   // (x,y) -> (y,x)
    ull r;
    asm("{\n\t.reg .b32 lo, hi;\n\tmov.b64 {lo, hi}, %1;\n\tmov.b64 %0, {hi, lo};\n\t}"
        : "=l"(r) : "l"(v));
    return r;
}
__device__ __forceinline__ ull f2mul(ull a, ull b) {
    ull r; asm("mul.rn.f32x2 %0, %1, %2;" : "=l"(r) : "l"(a), "l"(b)); return r;
}
__device__ __forceinline__ ull f2fma(ull a, ull b, ull c) {
    ull r; asm("fma.rn.f32x2 %0, %1, %2, %3;" : "=l"(r) : "l"(a), "l"(b), "l"(c)); return r;
}
__device__ __forceinline__ ull f2add(ull a, ull b) {
    ull r; asm("add.rn.f32x2 %0, %1, %2;" : "=l"(r) : "l"(a), "l"(b)); return r;
}

// smem slot swizzle: bijective, conflict-free for all phase patterns
__device__ __forceinline__ uint32_t sw(uint32_t i) { return i ^ ((i >> 4) & 0xFu); }

// base address: deposit 8 tid bits into the amplitude-index bits NOT in {P0..P3}
template<int P0, int P1, int P2, int P3>
__device__ __forceinline__ uint32_t phase_base(int tid) {
    constexpr uint32_t M = (1u << P0) | (1u << P1) | (1u << P2) | (1u << P3);
    uint32_t base = 0;
    int tb = 0;
#pragma unroll
    for (int pos = 0; pos < NQ; ++pos) {
        if (!((M >> pos) & 1u)) {
            base |= ((uint32_t)(tid >> tb) & 1u) << pos;
            ++tb;
        }
    }
    return base;
}

template<int P0, int P1, int P2, int P3>
__device__ __forceinline__ uint32_t pidx(uint32_t base, int j) {
    return base
        | ((j & 1) ? (1u << P0) : 0u)
        | ((j & 2) ? (1u << P1) : 0u)
        | ((j & 4) ? (1u << P2) : 0u)
        | ((j & 8) ? (1u << P3) : 0u);
}

// RY on register-bit RB:  a0' = c a0 - s a1 ; a1' = s a0 + c a1  (componentwise)
template<int RB>
__device__ __forceinline__ void gry(ull* r, float2 cs) {
    const ull c2 = dup2(cs.x), s2 = dup2(cs.y), ns2 = dup2(-cs.y);
#pragma unroll
    for (int j = 0; j < 16; ++j) {
        if (!(j & (1 << RB))) {
            ull a0 = r[j], a1 = r[j | (1 << RB)];
            r[j]            = f2fma(c2, a0, f2mul(ns2, a1));
            r[j | (1 << RB)] = f2fma(s2, a0, f2mul(c2, a1));
        }
    }
}

// CRX: control RBC==1, target RBT.  a0' = c a0 - i s a1 ; a1' = c a1 - i s a0.
//  -i s v = (s*v.y, -s*v.x) = mul((s,-s), swap(v))
template<int RBC, int RBT>
__device__ __forceinline__ void gcrx(ull* r, float2 cs) {
    const ull c2 = dup2(cs.x);
    const ull spm = pk2(cs.y, -cs.y);
#pragma unroll
    for (int j = 0; j < 16; ++j) {
        if ((j & (1 << RBC)) && !(j & (1 << RBT))) {
            ull a0 = r[j], a1 = r[j | (1 << RBT)];
            r[j]             = f2fma(c2, a0, f2mul(spm, swp(a1)));
            r[j | (1 << RBT)] = f2fma(c2, a1, f2mul(spm, swp(a0)));
        }
    }
}

#define PHASE_LOAD(P0,P1,P2,P3)                                            \
    uint32_t base = phase_base<P0,P1,P2,P3>(tid);                          \
    ull r[16];                                                             \
    _Pragma("unroll")                                                      \
    for (int j = 0; j < 16; ++j) r[j] = st[sw(pidx<P0,P1,P2,P3>(base, j))];

#define PHASE_STORE(P0,P1,P2,P3)                                           \
    _Pragma("unroll")                                                      \
    for (int j = 0; j < 16; ++j) st[sw(pidx<P0,P1,P2,P3>(base, j))] = r[j];

// ---- the 8 phases of one sim14 layer (wire w <-> amplitude bit 11-w) ----
// Layer = RY ring (idx 0..11) fused with chainA (idx 12..23), then RY ring
// (24..35) fused with chainB (36..47). Groupings preserve gate ordering.

__device__ __forceinline__ void phA1(ull* st, const float2* c, int tid) {
    PHASE_LOAD(11, 0, 1, 2);
    gry<0>(r, c[0]);  gry<1>(r, c[11]); gry<2>(r, c[10]); gry<3>(r, c[9]);
    gcrx<1, 0>(r, c[12]);
    gcrx<2, 1>(r, c[13]);
    gcrx<3, 2>(r, c[14]);
    PHASE_STORE(11, 0, 1, 2);
}
__device__ __forceinline__ void phA2(ull* st, const float2* c, int tid) {
    PHASE_LOAD(2, 3, 4, 5);
    gry<1>(r, c[8]); gry<2>(r, c[7]); gry<3>(r, c[6]);
    gcrx<1, 0>(r, c[15]);
    gcrx<2, 1>(r, c[16]);
    gcrx<3, 2>(r, c[17]);
    PHASE_STORE(2, 3, 4, 5);
}
__device__ __forceinline__ void phA3(ull* st, const float2* c, int tid) {
    PHASE_LOAD(5, 6, 7, 8);
    gry<1>(r, c[5]); gry<2>(r, c[4]); gry<3>(r, c[3]);
    gcrx<1, 0>(r, c[18]);
    gcrx<2, 1>(r, c[19]);
    gcrx<3, 2>(r, c[20]);
    PHASE_STORE(5, 6, 7, 8);
}
__device__ __forceinline__ void phA4(ull* st, const float2* c, int tid) {
    PHASE_LOAD(8, 9, 10, 11);
    gry<1>(r, c[2]); gry<2>(r, c[1]);
    gcrx<1, 0>(r, c[21]);
    gcrx<2, 1>(r, c[22]);
    gcrx<3, 2>(r, c[23]);
    PHASE_STORE(8, 9, 10, 11);
}
__device__ __forceinline__ void phB1(ull* st, const float2* c, int tid) {
    PHASE_LOAD(1, 0, 11, 10);
    gry<0>(r, c[34]); gry<1>(r, c[35]); gry<2>(r, c[24]); gry<3>(r, c[25]);
    gcrx<1, 0>(r, c[36]);
    gcrx<2, 1>(r, c[37]);
    gcrx<3, 2>(r, c[38]);
    PHASE_STORE(1, 0, 11, 10);
}
__device__ __forceinline__ void phB2(ull* st, const float2* c, int tid) {
    PHASE_LOAD(10, 9, 8, 7);
    gry<1>(r, c[26]); gry<2>(r, c[27]); gry<3>(r, c[28]);
    gcrx<1, 0>(r, c[39]);
    gcrx<2, 1>(r, c[40]);
    gcrx<3, 2>(r, c[41]);
    PHASE_STORE(10, 9, 8, 7);
}
__device__ __forceinline__ void phB3(ull* st, const float2* c, int tid) {
    PHASE_LOAD(7, 6, 5, 4);
    gry<1>(r, c[29]); gry<2>(r, c[30]); gry<3>(r, c[31]);
    gcrx<1, 0>(r, c[42]);
    gcrx<2, 1>(r, c[43]);
    gcrx<3, 2>(r, c[44]);
    PHASE_STORE(7, 6, 5, 4);
}
__device__ __forceinline__ void phB4(ull* st, const float2* c, int tid) {
    PHASE_LOAD(4, 3, 2, 1);
    gry<1>(r, c[32]); gry<2>(r, c[33]);
    gcrx<1, 0>(r, c[45]);
    gcrx<2, 1>(r, c[46]);
    gcrx<3, 2>(r, c[47]);
    PHASE_STORE(4, 3, 2, 1);
}

__device__ __forceinline__ void run_layer(ull* st, const float2* c, int tid) {
    phA1(st, c, tid); __syncthreads();
    phA2(st, c, tid); __syncthreads();
    phA3(st, c, tid); __syncthreads();
    phA4(st, c, tid); __syncthreads();
    phB1(st, c, tid); __syncthreads();
    phB2(st, c, tid); __syncthreads();
    phB3(st, c, tid); __syncthreads();
    phB4(st, c, tid); __syncthreads();
}

// ---------------------------------------------------------------------------
// Kernel 1: params. theta = sigmoid(x@W^T + b) * 2pi ; store (cos, sin)(theta/2)
// ---------------------------------------------------------------------------
__global__ void param_kernel(const float* __restrict__ x,
                             const float* __restrict__ Wp,
                             const float* __restrict__ bp,
                             const float* __restrict__ qff) {
    __shared__ float xr[FDIM];
    int bt = blockIdx.x;            // 0..2047
    int r = threadIdx.x;            // 0..95
    if (r < FDIM) xr[r] = x[bt * FDIM + r];
    __syncthreads();
    float acc = bp[r];
#pragma unroll
    for (int f = 0; f < FDIM; ++f) acc += xr[f] * Wp[r * FDIM + f];
    float sg = 1.0f / (1.0f + expf(-acc));
    float h = 3.14159265358979323846f * sg;   // theta/2 = pi * sigmoid
    g_cs[bt * NROTS + r] = make_float2(cosf(h), sinf(h));
    if (bt == 0 && r < QFFROTS) {
        float hq = 0.5f * qff[r];
        g_csqff[r] = make_float2(cosf(hq), sinf(hq));
    }
}

// ---------------------------------------------------------------------------
// Kernel 2: zero scratch, set work_0 = |0...0> per batch
// ---------------------------------------------------------------------------
__global__ void init_kernel() {
    uint32_t e = blockIdx.x * blockDim.x + threadIdx.x;   // 0 .. 5*64*4096-1
    float2* flat = &g_work[0][0];
    uint32_t buf = e >> 18;                 // /262144
    uint32_t rem = e & 0x3FFFFu;
    float2 v = make_float2(0.f, 0.f);
    if (buf == 0 && (rem & (DIM - 1)) == 0) v.x = 1.f;
    flat[e] = v;
}

// ---------------------------------------------------------------------------
// Kernel 3: one polynomial degree.
// grid = 1024 (b * 16 tgroups), each CTA runs TGROUP circuits and accumulates
// mix[t]*psi in registers, then RED.global into work_out.
// ---------------------------------------------------------------------------
__global__ void __launch_bounds__(256, 2)
circuit_kernel(const ull* __restrict__ win, float2* __restrict__ wout,
               const float* __restrict__ mix_re, const float* __restrict__ mix_im) {
    __shared__ ull st[DIM];
    const int tid = threadIdx.x;
    const int b = blockIdx.x >> 4;
    const int tg = blockIdx.x & 15;

    ull A[16];
#pragma unroll
    for (int j = 0; j < 16; ++j) A[j] = 0ull;

    for (int tt = 0; tt < TGROUP; ++tt) {
        const int t = tg * TGROUP + tt;
        __syncthreads();                      // prior iter readers done
#pragma unroll
        for (int k = 0; k < 16; ++k) {
            int i = tid + 256 * k;
            st[sw((uint32_t)i)] = win[b * DIM + i];
        }
        __syncthreads();

        const float2* c0 = &g_cs[(b * TSTEPS + t) * NROTS];
        run_layer(st, c0, tid);               // layer 0 (8 phases)
        const float2* c1 = c0 + 48;
        // layer 1: first 7 phases, last phase kept in registers
        phA1(st, c1, tid); __syncthreads();
        phA2(st, c1, tid); __syncthreads();
        phA3(st, c1, tid); __syncthreads();
        phA4(st, c1, tid); __syncthreads();
        phB1(st, c1, tid); __syncthreads();
        phB2(st, c1, tid); __syncthreads();
        phB3(st, c1, tid); __syncthreads();
        {   // phB4 without store: accumulate mix[t] * psi
            PHASE_LOAD(4, 3, 2, 1);
            gry<1>(r, c1[32]); gry<2>(r, c1[33]);
            gcrx<1, 0>(r, c1[45]);
            gcrx<2, 1>(r, c1[46]);
            gcrx<3, 2>(r, c1[47]);
            const float mr = mix_re[t], mi = mix_im[t];
            const ull mr2 = dup2(mr);
            const ull mpm = pk2(-mi, mi);     // mul(mpm, swap(v)) = (-mi*vy, mi*vx)
#pragma unroll
            for (int j = 0; j < 16; ++j) {
                A[j] = f2add(A[j], f2fma(mr2, r[j], f2mul(mpm, swp(r[j]))));
            }
        }
    }
    // flush accumulator (B4 amplitude mapping)
    uint32_t base = phase_base<4, 3, 2, 1>(tid);
#pragma unroll
    for (int j = 0; j < 16; ++j) {
        uint32_t i = pidx<4, 3, 2, 1>(base, j);
        float2 av = upk(A[j]);
        atomicAdd(&wout[b * DIM + i].x, av.x);
        atomicAdd(&wout[b * DIM + i].y, av.y);
    }
}

// ---------------------------------------------------------------------------
// Kernel 4: assemble acc, normalize, qff layer, Pauli expvals, output linear.
// grid = 64 (one CTA per batch), 256 threads.
// ---------------------------------------------------------------------------
__global__ void final_kernel(const float* __restrict__ poly,
                             const float* __restrict__ W_out,
                             const float* __restrict__ b_out,
                             float* __restrict__ out) {
    __shared__ ull st[DIM];
    __shared__ float red[37];            // [0..35] expvals, [36] sumsq
    const int tid = threadIdx.x;
    const int b = blockIdx.x;

    float p[DEGREE + 1];
#pragma unroll
    for (int d = 0; d <= DEGREE; ++d) p[d] = poly[d];
    float sabs = 0.f;
#pragma unroll
    for (int d = 0; d <= DEGREE; ++d) sabs += fabsf(p[d]);
    const float inv_s = 1.f / sabs;

    if (tid == 0) red[36] = 0.f;
    const ull* wflat = (const ull*)&g_work[0][0];
    float lsq = 0.f;
#pragma unroll
    for (int k = 0; k < 16; ++k) {
        int i = tid + 256 * k;
        ull v = 0ull;
#pragma unroll
        for (int d = 0; d <= DEGREE; ++d) {
            ull w = wflat[(size_t)d * (BATCH * DIM) + b * DIM + i];
            v = f2fma(dup2(p[d]), w, v);
        }
        v = f2mul(dup2(inv_s), v);
        st[sw((uint32_t)i)] = v;
        float2 vf = upk(v);
        lsq += vf.x * vf.x + vf.y * vf.y;
    }
#pragma unroll
    for (int o = 16; o > 0; o >>= 1) lsq += __shfl_xor_sync(0xffffffffu, lsq, o);
    if ((tid & 31) == 0) atomicAdd(&red[36], lsq);
    __syncthreads();

    const float f = 1.f / (sqrtf(red[36]) + 1e-9f);
    const ull f2 = dup2(f);
#pragma unroll
    for (int k = 0; k < 16; ++k) {
        int i = tid + 256 * k;
        uint32_t s_ = sw((uint32_t)i);
        st[s_] = f2mul(f2, st[s_]);
    }
    __syncthreads();

    run_layer(st, g_csqff, tid);     // qff: one sim14 layer

    if (tid < 36) red[tid] = 0.f;
    __syncthreads();

    float xx[NQ], yy[NQ], zz[NQ];
#pragma unroll
    for (int w = 0; w < NQ; ++w) { xx[w] = 0.f; yy[w] = 0.f; zz[w] = 0.f; }

#pragma unroll
    for (int k = 0; k < 16; ++k) {
        int i = tid + 256 * k;
        float2 a = upk(st[sw((uint32_t)i)]);
        float n2 = a.x * a.x + a.y * a.y;
#pragma unroll
        for (int w = 0; w < NQ; ++w) {
            int pbit = 11 - w;
            if (((i >> pbit) & 1) == 0) {
                float2 a1 = upk(st[sw((uint32_t)(i | (1 << pbit)))]);
                xx[w] += 2.f * (a.x * a1.x + a.y * a1.y);
                yy[w] += 2.f * (a.x * a1.y - a.y * a1.x);
                zz[w] += n2;
            } else {
                zz[w] -= n2;
            }
        }
    }
#pragma unroll
    for (int w = 0; w < NQ; ++w) {
        atomicAdd(&red[w], xx[w]);
        atomicAdd(&red[12 + w], yy[w]);
        atomicAdd(&red[24 + w], zz[w]);
    }
    __syncthreads();

    if (tid < ODIM) {
        float acc = b_out[tid];
#pragma unroll
        for (int j = 0; j < 36; ++j) acc += W_out[tid * 36 + j] * red[j];
        out[b * ODIM + tid] = acc;
    }
}

// ---------------------------------------------------------------------------
// Inputs (metadata order): x, W_proj, b_proj, poly_coeffs, mix_re, mix_im,
//                          qff_params, W_out, b_out.  Output: float32 [64,8].
// ---------------------------------------------------------------------------
extern "C" void kernel_launch(void* const* d_in, const int* in_sizes, int n_in,
                              void* d_out, int out_size) {
    (void)in_sizes; (void)n_in; (void)out_size;
    const float* x      = (const float*)d_in[0];
    const float* W_proj = (const float*)d_in[1];
    const float* b_proj = (const float*)d_in[2];
    const float* poly   = (const float*)d_in[3];
    const float* mix_re = (const float*)d_in[4];
    const float* mix_im = (const float*)d_in[5];
    const float* qff    = (const float*)d_in[6];
    const float* W_out  = (const float*)d_in[7];
    const float* b_out  = (const float*)d_in[8];
    float* out = (float*)d_out;

    param_kernel<<<BATCH * TSTEPS, NROTS>>>(x, W_proj, b_proj, qff);
    init_kernel<<<(DEGREE + 1) * BATCH * DIM / 256, 256>>>();

    float2* w0;
    cudaGetSymbolAddress((void**)&w0, g_work);   // base of g_work
    float2* w1 = w0 + 1 * BATCH * DIM;
    float2* w2 = w0 + 2 * BATCH * DIM;
    float2* w3 = w0 + 3 * BATCH * DIM;
    float2* w4 = w0 + 4 * BATCH * DIM;

    circuit_kernel<<<NBLK_CIRC, 256>>>((const ull*)w0, w1, mix_re, mix_im);
    circuit_kernel<<<NBLK_CIRC, 256>>>((const ull*)w1, w2, mix_re, mix_im);
    circuit_kernel<<<NBLK_CIRC, 256>>>((const ull*)w2, w3, mix_re, mix_im);
    circuit_kernel<<<NBLK_CIRC, 256>>>((const ull*)w3, w4, mix_re, mix_im);

    final_kernel<<<BATCH, 256>>>(poly, W_out, b_out, out);
}

// round 6
// speedup vs baseline: 1.1229x; 1.0965x over previous
#include <cuda_runtime.h>
#include <cuda_bf16.h>
#include <math.h>
#include <stdint.h>

// ---------------------------------------------------------------------------
// QuantumTSTransformer: 12-qubit statevector sim, packed f32x2 arithmetic.
//   B=64, T=32, DEGREE=4, sim14 2 layers (96 rots), qff layer (48), DIM=4096.
// circuit_kernel: one CTA per (b, t-pair); state in dynamic smem (32KB) as
// packed (re,im) b64; gates in 8 phases/layer, 4 register-resident qubits
// (16 packed amps/thread, 256 threads). Coefficients staged in smem. Mix-
// weighted accumulator in a second 32KB smem buffer (no A registers) so
// __launch_bounds__(256,3) gives 3 CTAs/SM. Flush via red.global.add.v2.f32.
// ---------------------------------------------------------------------------

#define NQ       12
#define DIM      4096
#define BATCH    64
#define TSTEPS   32
#define NROTS    96
#define QFFROTS  48
#define DEGREE   4
#define FDIM     64
#define ODIM     8
#define TGROUP   2                     // t-values per CTA in circuit kernel
#define NBLK_CIRC (BATCH * (TSTEPS / TGROUP))   // 1024
#define CIRC_SMEM (2 * DIM * 8 + 1024)          // st + acc + coeffs

typedef unsigned long long ull;

// Scratch (device globals: no allocation allowed)
__device__ float2 g_work[DEGREE + 1][BATCH * DIM];   // work_0=base, work_1..4
__device__ float2 g_cs[BATCH * TSTEPS * NROTS];      // (cos(h), sin(h)) per rot
__device__ float2 g_csqff[QFFROTS];

// ---------------- packed f32x2 helpers ----------------
__device__ __forceinline__ ull pk2(float x, float y) {
    ull r; asm("mov.b64 %0, {%1, %2};" : "=l"(r) : "f"(x), "f"(y)); return r;
}
__device__ __forceinline__ ull dup2(float x) { return pk2(x, x); }
__device__ __forceinline__ float2 upk(ull v) {
    float2 r; asm("mov.b64 {%0, %1}, %2;" : "=f"(r.x), "=f"(r.y) : "l"(v)); return r;
}
__device__ __forceinline__ ull swp(ull v) {   // (x,y) -> (y,x)
    ull r;
    asm("{\n\t.reg .b32 lo, hi;\n\tmov.b64 {lo, hi}, %1;\n\tmov.b64 %0, {hi, lo};\n\t}"
        : "=l"(r) : "l"(v));
    return r;
}
__device__ __forceinline__ ull f2mul(ull a, ull b) {
    ull r; asm("mul.rn.f32x2 %0, %1, %2;" : "=l"(r) : "l"(a), "l"(b)); return r;
}
__device__ __forceinline__ ull f2fma(ull a, ull b, ull c) {
    ull r; asm("fma.rn.f32x2 %0, %1, %2, %3;" : "=l"(r) : "l"(a), "l"(b), "l"(c)); return r;
}
__device__ __forceinline__ ull f2add(ull a, ull b) {
    ull r; asm("add.rn.f32x2 %0, %1, %2;" : "=l"(r) : "l"(a), "l"(b)); return r;
}
__device__ __forceinline__ void red2(float2* p, float2 v) {
    asm volatile("red.global.add.v2.f32 [%0], {%1, %2};"
                 :: "l"(p), "f"(v.x), "f"(v.y) : "memory");
}

// smem slot swizzle: bijective, conflict-free for all phase patterns
__device__ __forceinline__ uint32_t sw(uint32_t i) { return i ^ ((i >> 4) & 0xFu); }

// base address: deposit 8 tid bits into the amplitude-index bits NOT in {P0..P3}
template<int P0, int P1, int P2, int P3>
__device__ __forceinline__ uint32_t phase_base(int tid) {
    constexpr uint32_t M = (1u << P0) | (1u << P1) | (1u << P2) | (1u << P3);
    uint32_t base = 0;
    int tb = 0;
#pragma unroll
    for (int pos = 0; pos < NQ; ++pos) {
        if (!((M >> pos) & 1u)) {
            base |= ((uint32_t)(tid >> tb) & 1u) << pos;
            ++tb;
        }
    }
    return base;
}

template<int P0, int P1, int P2, int P3>
__device__ __forceinline__ uint32_t pidx(uint32_t base, int j) {
    return base
        | ((j & 1) ? (1u << P0) : 0u)
        | ((j & 2) ? (1u << P1) : 0u)
        | ((j & 4) ? (1u << P2) : 0u)
        | ((j & 8) ? (1u << P3) : 0u);
}

// RY on register-bit RB:  a0' = c a0 - s a1 ; a1' = s a0 + c a1  (componentwise)
template<int RB>
__device__ __forceinline__ void gry(ull* r, float2 cs) {
    const ull c2 = dup2(cs.x), s2 = dup2(cs.y), ns2 = dup2(-cs.y);
#pragma unroll
    for (int j = 0; j < 16; ++j) {
        if (!(j & (1 << RB))) {
            ull a0 = r[j], a1 = r[j | (1 << RB)];
            r[j]            = f2fma(c2, a0, f2mul(ns2, a1));
            r[j | (1 << RB)] = f2fma(s2, a0, f2mul(c2, a1));
        }
    }
}

// CRX: control RBC==1, target RBT.  a0' = c a0 - i s a1 ; a1' = c a1 - i s a0.
//  -i s v = (s*v.y, -s*v.x) = mul((s,-s), swap(v))
template<int RBC, int RBT>
__device__ __forceinline__ void gcrx(ull* r, float2 cs) {
    const ull c2 = dup2(cs.x);
    const ull spm = pk2(cs.y, -cs.y);
#pragma unroll
    for (int j = 0; j < 16; ++j) {
        if ((j & (1 << RBC)) && !(j & (1 << RBT))) {
            ull a0 = r[j], a1 = r[j | (1 << RBT)];
            r[j]             = f2fma(c2, a0, f2mul(spm, swp(a1)));
            r[j | (1 << RBT)] = f2fma(c2, a1, f2mul(spm, swp(a0)));
        }
    }
}

#define PHASE_LOAD(P0,P1,P2,P3)                                            \
    uint32_t base = phase_base<P0,P1,P2,P3>(tid);                          \
    ull r[16];                                                             \
    _Pragma("unroll")                                                      \
    for (int j = 0; j < 16; ++j) r[j] = st[sw(pidx<P0,P1,P2,P3>(base, j))];

#define PHASE_STORE(P0,P1,P2,P3)                                           \
    _Pragma("unroll")                                                      \
    for (int j = 0; j < 16; ++j) st[sw(pidx<P0,P1,P2,P3>(base, j))] = r[j];

// ---- the 8 phases of one sim14 layer (wire w <-> amplitude bit 11-w) ----
// Layer = RY ring (idx 0..11) fused with chainA (idx 12..23), then RY ring
// (24..35) fused with chainB (36..47). Groupings preserve gate ordering.

__device__ __forceinline__ void phA1(ull* st, const float2* c, int tid) {
    PHASE_LOAD(11, 0, 1, 2);
    gry<0>(r, c[0]);  gry<1>(r, c[11]); gry<2>(r, c[10]); gry<3>(r, c[9]);
    gcrx<1, 0>(r, c[12]);
    gcrx<2, 1>(r, c[13]);
    gcrx<3, 2>(r, c[14]);
    PHASE_STORE(11, 0, 1, 2);
}
__device__ __forceinline__ void phA2(ull* st, const float2* c, int tid) {
    PHASE_LOAD(2, 3, 4, 5);
    gry<1>(r, c[8]); gry<2>(r, c[7]); gry<3>(r, c[6]);
    gcrx<1, 0>(r, c[15]);
    gcrx<2, 1>(r, c[16]);
    gcrx<3, 2>(r, c[17]);
    PHASE_STORE(2, 3, 4, 5);
}
__device__ __forceinline__ void phA3(ull* st, const float2* c, int tid) {
    PHASE_LOAD(5, 6, 7, 8);
    gry<1>(r, c[5]); gry<2>(r, c[4]); gry<3>(r, c[3]);
    gcrx<1, 0>(r, c[18]);
    gcrx<2, 1>(r, c[19]);
    gcrx<3, 2>(r, c[20]);
    PHASE_STORE(5, 6, 7, 8);
}
__device__ __forceinline__ void phA4(ull* st, const float2* c, int tid) {
    PHASE_LOAD(8, 9, 10, 11);
    gry<1>(r, c[2]); gry<2>(r, c[1]);
    gcrx<1, 0>(r, c[21]);
    gcrx<2, 1>(r, c[22]);
    gcrx<3, 2>(r, c[23]);
    PHASE_STORE(8, 9, 10, 11);
}
__device__ __forceinline__ void phB1(ull* st, const float2* c, int tid) {
    PHASE_LOAD(1, 0, 11, 10);
    gry<0>(r, c[34]); gry<1>(r, c[35]); gry<2>(r, c[24]); gry<3>(r, c[25]);
    gcrx<1, 0>(r, c[36]);
    gcrx<2, 1>(r, c[37]);
    gcrx<3, 2>(r, c[38]);
    PHASE_STORE(1, 0, 11, 10);
}
__device__ __forceinline__ void phB2(ull* st, const float2* c, int tid) {
    PHASE_LOAD(10, 9, 8, 7);
    gry<1>(r, c[26]); gry<2>(r, c[27]); gry<3>(r, c[28]);
    gcrx<1, 0>(r, c[39]);
    gcrx<2, 1>(r, c[40]);
    gcrx<3, 2>(r, c[41]);
    PHASE_STORE(10, 9, 8, 7);
}
__device__ __forceinline__ void phB3(ull* st, const float2* c, int tid) {
    PHASE_LOAD(7, 6, 5, 4);
    gry<1>(r, c[29]); gry<2>(r, c[30]); gry<3>(r, c[31]);
    gcrx<1, 0>(r, c[42]);
    gcrx<2, 1>(r, c[43]);
    gcrx<3, 2>(r, c[44]);
    PHASE_STORE(7, 6, 5, 4);
}
__device__ __forceinline__ void phB4(ull* st, const float2* c, int tid) {
    PHASE_LOAD(4, 3, 2, 1);
    gry<1>(r, c[32]); gry<2>(r, c[33]);
    gcrx<1, 0>(r, c[45]);
    gcrx<2, 1>(r, c[46]);
    gcrx<3, 2>(r, c[47]);
    PHASE_STORE(4, 3, 2, 1);
}

__device__ __forceinline__ void run_layer(ull* st, const float2* c, int tid) {
    phA1(st, c, tid); __syncthreads();
    phA2(st, c, tid); __syncthreads();
    phA3(st, c, tid); __syncthreads();
    phA4(st, c, tid); __syncthreads();
    phB1(st, c, tid); __syncthreads();
    phB2(st, c, tid); __syncthreads();
    phB3(st, c, tid); __syncthreads();
    phB4(st, c, tid); __syncthreads();
}

// ---------------------------------------------------------------------------
// Kernel 1: params. theta = sigmoid(x@W^T + b) * 2pi ; store (cos, sin)(theta/2)
// ---------------------------------------------------------------------------
__global__ void param_kernel(const float* __restrict__ x,
                             const float* __restrict__ Wp,
                             const float* __restrict__ bp,
                             const float* __restrict__ qff) {
    __shared__ float xr[FDIM];
    int bt = blockIdx.x;            // 0..2047
    int r = threadIdx.x;            // 0..95
    if (r < FDIM) xr[r] = x[bt * FDIM + r];
    __syncthreads();
    float acc = bp[r];
#pragma unroll
    for (int f = 0; f < FDIM; ++f) acc += xr[f] * Wp[r * FDIM + f];
    float sg = 1.0f / (1.0f + expf(-acc));
    float h = 3.14159265358979323846f * sg;   // theta/2 = pi * sigmoid
    float sv, cv; sincosf(h, &sv, &cv);
    g_cs[bt * NROTS + r] = make_float2(cv, sv);
    if (bt == 0 && r < QFFROTS) {
        float hq = 0.5f * qff[r];
        float sq, cq; sincosf(hq, &sq, &cq);
        g_csqff[r] = make_float2(cq, sq);
    }
}

// ---------------------------------------------------------------------------
// Kernel 2: zero scratch, set work_0 = |0...0> per batch
// ---------------------------------------------------------------------------
__global__ void init_kernel() {
    uint32_t e = blockIdx.x * blockDim.x + threadIdx.x;   // 0 .. 5*64*4096-1
    float2* flat = &g_work[0][0];
    uint32_t buf = e >> 18;                 // /262144
    uint32_t rem = e & 0x3FFFFu;
    float2 v = make_float2(0.f, 0.f);
    if (buf == 0 && (rem & (DIM - 1)) == 0) v.x = 1.f;
    flat[e] = v;
}

// ---------------------------------------------------------------------------
// Kernel 3: one polynomial degree.
// grid = 1024 (b * 16 tgroups). Dynamic smem: st[DIM] + acc[DIM] + coeffs.
// Each CTA runs TGROUP circuits, accumulating mix[t]*psi in smem acc, then
// flushes with red.global.add.v2.f32 into work_out.
// ---------------------------------------------------------------------------
__global__ void __launch_bounds__(256, 3)
circuit_kernel(const ull* __restrict__ win, float2* __restrict__ wout,
               const float* __restrict__ mix_re, const float* __restrict__ mix_im) {
    extern __shared__ ull dsm[];
    ull* st  = dsm;                 // DIM
    ull* acc = dsm + DIM;           // DIM
    float2* cc = (float2*)(dsm + 2 * DIM);   // 96 coeffs + mix at [96]

    const int tid = threadIdx.x;
    const int b = blockIdx.x >> 4;
    const int tg = blockIdx.x & 15;

    // zero the smem accumulator
#pragma unroll
    for (int k = 0; k < 16; ++k) acc[tid + 256 * k] = 0ull;

    for (int tt = 0; tt < TGROUP; ++tt) {
        const int t = tg * TGROUP + tt;
        __syncthreads();                      // prior iter readers done
#pragma unroll
        for (int k = 0; k < 16; ++k) {
            int i = tid + 256 * k;
            st[sw((uint32_t)i)] = win[b * DIM + i];
        }
        if (tid < NROTS) cc[tid] = g_cs[(b * TSTEPS + t) * NROTS + tid];
        if (tid == NROTS) cc[NROTS] = make_float2(mix_re[t], mix_im[t]);
        __syncthreads();

        run_layer(st, cc, tid);               // layer 0 (8 phases)
        const float2* c1 = cc + 48;
        // layer 1: first 7 phases, last phase kept in registers
        phA1(st, c1, tid); __syncthreads();
        phA2(st, c1, tid); __syncthreads();
        phA3(st, c1, tid); __syncthreads();
        phA4(st, c1, tid); __syncthreads();
        phB1(st, c1, tid); __syncthreads();
        phB2(st, c1, tid); __syncthreads();
        phB3(st, c1, tid); __syncthreads();
        {   // phB4 without store: accumulate mix[t] * psi into smem acc
            PHASE_LOAD(4, 3, 2, 1);
            gry<1>(r, c1[32]); gry<2>(r, c1[33]);
            gcrx<1, 0>(r, c1[45]);
            gcrx<2, 1>(r, c1[46]);
            gcrx<3, 2>(r, c1[47]);
            float2 mx = cc[NROTS];
            const ull mr2 = dup2(mx.x);
            const ull mpm = pk2(-mx.y, mx.y); // mul(mpm, swap(v)) = (-mi*vy, mi*vx)
#pragma unroll
            for (int j = 0; j < 16; ++j) {
                uint32_t a = sw(pidx<4, 3, 2, 1>(base, j));
                acc[a] = f2add(acc[a], f2fma(mr2, r[j], f2mul(mpm, swp(r[j]))));
            }
        }
    }
    __syncthreads();
    // flush accumulator: linear read (conflict-free), vector reduction to global
#pragma unroll
    for (int k = 0; k < 16; ++k) {
        int i = tid + 256 * k;
        red2(&wout[b * DIM + i], upk(acc[sw((uint32_t)i)]));
    }
}

// ---------------------------------------------------------------------------
// Kernel 4: assemble acc, normalize, qff layer, Pauli expvals, output linear.
// grid = 64 (one CTA per batch), 256 threads.
// ---------------------------------------------------------------------------
__global__ void final_kernel(const float* __restrict__ poly,
                             const float* __restrict__ W_out,
                             const float* __restrict__ b_out,
                             float* __restrict__ out) {
    __shared__ ull st[DIM];
    __shared__ float red[37];            // [0..35] expvals, [36] sumsq
    const int tid = threadIdx.x;
    const int b = blockIdx.x;

    float p[DEGREE + 1];
#pragma unroll
    for (int d = 0; d <= DEGREE; ++d) p[d] = poly[d];
    float sabs = 0.f;
#pragma unroll
    for (int d = 0; d <= DEGREE; ++d) sabs += fabsf(p[d]);
    const float inv_s = 1.f / sabs;

    if (tid == 0) red[36] = 0.f;
    const ull* wflat = (const ull*)&g_work[0][0];
    float lsq = 0.f;
#pragma unroll
    for (int k = 0; k < 16; ++k) {
        int i = tid + 256 * k;
        ull v = 0ull;
#pragma unroll
        for (int d = 0; d <= DEGREE; ++d) {
            ull w = wflat[(size_t)d * (BATCH * DIM) + b * DIM + i];
            v = f2fma(dup2(p[d]), w, v);
        }
        v = f2mul(dup2(inv_s), v);
        st[sw((uint32_t)i)] = v;
        float2 vf = upk(v);
        lsq += vf.x * vf.x + vf.y * vf.y;
    }
#pragma unroll
    for (int o = 16; o > 0; o >>= 1) lsq += __shfl_xor_sync(0xffffffffu, lsq, o);
    if ((tid & 31) == 0) atomicAdd(&red[36], lsq);
    __syncthreads();

    const float f = 1.f / (sqrtf(red[36]) + 1e-9f);
    const ull f2 = dup2(f);
#pragma unroll
    for (int k = 0; k < 16; ++k) {
        int i = tid + 256 * k;
        uint32_t s_ = sw((uint32_t)i);
        st[s_] = f2mul(f2, st[s_]);
    }
    __syncthreads();

    run_layer(st, g_csqff, tid);     // qff: one sim14 layer

    if (tid < 36) red[tid] = 0.f;
    __syncthreads();

    float xx[NQ], yy[NQ], zz[NQ];
#pragma unroll
    for (int w = 0; w < NQ; ++w) { xx[w] = 0.f; yy[w] = 0.f; zz[w] = 0.f; }

#pragma unroll
    for (int k = 0; k < 16; ++k) {
        int i = tid + 256 * k;
        float2 a = upk(st[sw((uint32_t)i)]);
        float n2 = a.x * a.x + a.y * a.y;
#pragma unroll
        for (int w = 0; w < NQ; ++w) {
            int pbit = 11 - w;
            if (((i >> pbit) & 1) == 0) {
                float2 a1 = upk(st[sw((uint32_t)(i | (1 << pbit)))]);
                xx[w] += 2.f * (a.x * a1.x + a.y * a1.y);
                yy[w] += 2.f * (a.x * a1.y - a.y * a1.x);
                zz[w] += n2;
            } else {
                zz[w] -= n2;
            }
        }
    }
#pragma unroll
    for (int w = 0; w < NQ; ++w) {
        atomicAdd(&red[w], xx[w]);
        atomicAdd(&red[12 + w], yy[w]);
        atomicAdd(&red[24 + w], zz[w]);
    }
    __syncthreads();

    if (tid < ODIM) {
        float acc = b_out[tid];
#pragma unroll
        for (int j = 0; j < 36; ++j) acc += W_out[tid * 36 + j] * red[j];
        out[b * ODIM + tid] = acc;
    }
}

// ---------------------------------------------------------------------------
// Inputs (metadata order): x, W_proj, b_proj, poly_coeffs, mix_re, mix_im,
//                          qff_params, W_out, b_out.  Output: float32 [64,8].
// ---------------------------------------------------------------------------
extern "C" void kernel_launch(void* const* d_in, const int* in_sizes, int n_in,
                              void* d_out, int out_size) {
    (void)in_sizes; (void)n_in; (void)out_size;
    const float* x      = (const float*)d_in[0];
    const float* W_proj = (const float*)d_in[1];
    const float* b_proj = (const float*)d_in[2];
    const float* poly   = (const float*)d_in[3];
    const float* mix_re = (const float*)d_in[4];
    const float* mix_im = (const float*)d_in[5];
    const float* qff    = (const float*)d_in[6];
    const float* W_out  = (const float*)d_in[7];
    const float* b_out  = (const float*)d_in[8];
    float* out = (float*)d_out;

    cudaFuncSetAttribute(circuit_kernel,
                         cudaFuncAttributeMaxDynamicSharedMemorySize, CIRC_SMEM);

    param_kernel<<<BATCH * TSTEPS, NROTS>>>(x, W_proj, b_proj, qff);
    init_kernel<<<(DEGREE + 1) * BATCH * DIM / 256, 256>>>();

    float2* w0;
    cudaGetSymbolAddress((void**)&w0, g_work);   // base of g_work
    float2* w1 = w0 + 1 * BATCH * DIM;
    float2* w2 = w0 + 2 * BATCH * DIM;
    float2* w3 = w0 + 3 * BATCH * DIM;
    float2* w4 = w0 + 4 * BATCH * DIM;

    circuit_kernel<<<NBLK_CIRC, 256, CIRC_SMEM>>>((const ull*)w0, w1, mix_re, mix_im);
    circuit_kernel<<<NBLK_CIRC, 256, CIRC_SMEM>>>((const ull*)w1, w2, mix_re, mix_im);
    circuit_kernel<<<NBLK_CIRC, 256, CIRC_SMEM>>>((const ull*)w2, w3, mix_re, mix_im);
    circuit_kernel<<<NBLK_CIRC, 256, CIRC_SMEM>>>((const ull*)w3, w4, mix_re, mix_im);

    final_kernel<<<BATCH, 256>>>(poly, W_out, b_out, out);
}

// round 8
// speedup vs baseline: 1.1506x; 1.0247x over previous
#include <cuda_runtime.h>
#include <cuda_bf16.h>
#include <math.h>
#include <stdint.h>

// ---------------------------------------------------------------------------
// QuantumTSTransformer: 12-qubit statevector sim, packed f32x2 arithmetic.
//   B=64, T=32, DEGREE=4, sim14 2 layers (96 rots), qff layer (48), DIM=4096.
// circuit_kernel: one CTA per (b, t); state in dynamic smem (32KB) as packed
// (re,im) b64; gates in 8 phases/layer, 4 register-resident qubits (16 packed
// amps/thread, 256 threads). Coefficients staged in smem. Final phase fuses
// mix[t]*psi and flushes directly via red.global.add.v2.f32 (no accumulator),
// so __launch_bounds__(256,4) gives 4 CTAs/SM (32 warps).
// ---------------------------------------------------------------------------

#define NQ       12
#define DIM      4096
#define BATCH    64
#define TSTEPS   32
#define NROTS    96
#define QFFROTS  48
#define DEGREE   4
#define FDIM     64
#define ODIM     8
#define NBLK_CIRC (BATCH * TSTEPS)              // 2048
#define CIRC_SMEM (DIM * 8 + 1024)              // st + coeffs

typedef unsigned long long ull;

// Scratch (device globals: no allocation allowed)
__device__ float2 g_work[DEGREE + 1][BATCH * DIM];   // work_0=base, work_1..4
__device__ float2 g_cs[BATCH * TSTEPS * NROTS];      // (cos(h), sin(h)) per rot
__device__ float2 g_csqff[QFFROTS];

// ---------------- packed f32x2 helpers ----------------
__device__ __forceinline__ ull pk2(float x, float y) {
    ull r; asm("mov.b64 %0, {%1, %2};" : "=l"(r) : "f"(x), "f"(y)); return r;
}
__device__ __forceinline__ ull dup2(float x) { return pk2(x, x); }
__device__ __forceinline__ float2 upk(ull v) {
    float2 r; asm("mov.b64 {%0, %1}, %2;" : "=f"(r.x), "=f"(r.y) : "l"(v)); return r;
}
__device__ __forceinline__ ull swp(ull v) {   // (x,y) -> (y,x)
    ull r;
    asm("{\n\t.reg .b32 lo, hi;\n\tmov.b64 {lo, hi}, %1;\n\tmov.b64 %0, {hi, lo};\n\t}"
        : "=l"(r) : "l"(v));
    return r;
}
__device__ __forceinline__ ull f2mul(ull a, ull b) {
    ull r; asm("mul.rn.f32x2 %0, %1, %2;" : "=l"(r) : "l"(a), "l"(b)); return r;
}
__device__ __forceinline__ ull f2fma(ull a, ull b, ull c) {
    ull r; asm("fma.rn.f32x2 %0, %1, %2, %3;" : "=l"(r) : "l"(a), "l"(b), "l"(c)); return r;
}
__device__ __forceinline__ void red2(float2* p, float2 v) {
    asm volatile("red.global.add.v2.f32 [%0], {%1, %2};"
                 :: "l"(p), "f"(v.x), "f"(v.y) : "memory");
}

// smem slot swizzle: bijective, conflict-free for all phase patterns
__device__ __forceinline__ uint32_t sw(uint32_t i) { return i ^ ((i >> 4) & 0xFu); }

// base address: deposit 8 tid bits into the amplitude-index bits NOT in {P0..P3}
template<int P0, int P1, int P2, int P3>
__device__ __forceinline__ uint32_t phase_base(int tid) {
    constexpr uint32_t M = (1u << P0) | (1u << P1) | (1u << P2) | (1u << P3);
    uint32_t base = 0;
    int tb = 0;
#pragma unroll
    for (int pos = 0; pos < NQ; ++pos) {
        if (!((M >> pos) & 1u)) {
            base |= ((uint32_t)(tid >> tb) & 1u) << pos;
            ++tb;
        }
    }
    return base;
}

template<int P0, int P1, int P2, int P3>
__device__ __forceinline__ uint32_t pidx(uint32_t base, int j) {
    return base
        | ((j & 1) ? (1u << P0) : 0u)
        | ((j & 2) ? (1u << P1) : 0u)
        | ((j & 4) ? (1u << P2) : 0u)
        | ((j & 8) ? (1u << P3) : 0u);
}

// RY on register-bit RB:  a0' = c a0 - s a1 ; a1' = s a0 + c a1  (componentwise)
template<int RB>
__device__ __forceinline__ void gry(ull* r, float2 cs) {
    const ull c2 = dup2(cs.x), s2 = dup2(cs.y), ns2 = dup2(-cs.y);
#pragma unroll
    for (int j = 0; j < 16; ++j) {
        if (!(j & (1 << RB))) {
            ull a0 = r[j], a1 = r[j | (1 << RB)];
            r[j]            = f2fma(c2, a0, f2mul(ns2, a1));
            r[j | (1 << RB)] = f2fma(s2, a0, f2mul(c2, a1));
        }
    }
}

// CRX: control RBC==1, target RBT.  a0' = c a0 - i s a1 ; a1' = c a1 - i s a0.
//  -i s v = (s*v.y, -s*v.x) = mul((s,-s), swap(v))
template<int RBC, int RBT>
__device__ __forceinline__ void gcrx(ull* r, float2 cs) {
    const ull c2 = dup2(cs.x);
    const ull spm = pk2(cs.y, -cs.y);
#pragma unroll
    for (int j = 0; j < 16; ++j) {
        if ((j & (1 << RBC)) && !(j & (1 << RBT))) {
            ull a0 = r[j], a1 = r[j | (1 << RBT)];
            r[j]             = f2fma(c2, a0, f2mul(spm, swp(a1)));
            r[j | (1 << RBT)] = f2fma(c2, a1, f2mul(spm, swp(a0)));
        }
    }
}

#define PHASE_LOAD(P0,P1,P2,P3)                                            \
    uint32_t base = phase_base<P0,P1,P2,P3>(tid);                          \
    ull r[16];                                                             \
    _Pragma("unroll")                                                      \
    for (int j = 0; j < 16; ++j) r[j] = st[sw(pidx<P0,P1,P2,P3>(base, j))];

#define PHASE_STORE(P0,P1,P2,P3)                                           \
    _Pragma("unroll")                                                      \
    for (int j = 0; j < 16; ++j) st[sw(pidx<P0,P1,P2,P3>(base, j))] = r[j];

// ---- the 8 phases of one sim14 layer (wire w <-> amplitude bit 11-w) ----
// Layer = RY ring (idx 0..11) fused with chainA (idx 12..23), then RY ring
// (24..35) fused with chainB (36..47). Groupings preserve gate ordering.

__device__ __forceinline__ void phA1(ull* st, const float2* c, int tid) {
    PHASE_LOAD(11, 0, 1, 2);
    gry<0>(r, c[0]);  gry<1>(r, c[11]); gry<2>(r, c[10]); gry<3>(r, c[9]);
    gcrx<1, 0>(r, c[12]);
    gcrx<2, 1>(r, c[13]);
    gcrx<3, 2>(r, c[14]);
    PHASE_STORE(11, 0, 1, 2);
}
__device__ __forceinline__ void phA2(ull* st, const float2* c, int tid) {
    PHASE_LOAD(2, 3, 4, 5);
    gry<1>(r, c[8]); gry<2>(r, c[7]); gry<3>(r, c[6]);
    gcrx<1, 0>(r, c[15]);
    gcrx<2, 1>(r, c[16]);
    gcrx<3, 2>(r, c[17]);
    PHASE_STORE(2, 3, 4, 5);
}
__device__ __forceinline__ void phA3(ull* st, const float2* c, int tid) {
    PHASE_LOAD(5, 6, 7, 8);
    gry<1>(r, c[5]); gry<2>(r, c[4]); gry<3>(r, c[3]);
    gcrx<1, 0>(r, c[18]);
    gcrx<2, 1>(r, c[19]);
    gcrx<3, 2>(r, c[20]);
    PHASE_STORE(5, 6, 7, 8);
}
__device__ __forceinline__ void phA4(ull* st, const float2* c, int tid) {
    PHASE_LOAD(8, 9, 10, 11);
    gry<1>(r, c[2]); gry<2>(r, c[1]);
    gcrx<1, 0>(r, c[21]);
    gcrx<2, 1>(r, c[22]);
    gcrx<3, 2>(r, c[23]);
    PHASE_STORE(8, 9, 10, 11);
}
__device__ __forceinline__ void phB1(ull* st, const float2* c, int tid) {
    PHASE_LOAD(1, 0, 11, 10);
    gry<0>(r, c[34]); gry<1>(r, c[35]); gry<2>(r, c[24]); gry<3>(r, c[25]);
    gcrx<1, 0>(r, c[36]);
    gcrx<2, 1>(r, c[37]);
    gcrx<3, 2>(r, c[38]);
    PHASE_STORE(1, 0, 11, 10);
}
__device__ __forceinline__ void phB2(ull* st, const float2* c, int tid) {
    PHASE_LOAD(10, 9, 8, 7);
    gry<1>(r, c[26]); gry<2>(r, c[27]); gry<3>(r, c[28]);
    gcrx<1, 0>(r, c[39]);
    gcrx<2, 1>(r, c[40]);
    gcrx<3, 2>(r, c[41]);
    PHASE_STORE(10, 9, 8, 7);
}
__device__ __forceinline__ void phB3(ull* st, const float2* c, int tid) {
    PHASE_LOAD(7, 6, 5, 4);
    gry<1>(r, c[29]); gry<2>(r, c[30]); gry<3>(r, c[31]);
    gcrx<1, 0>(r, c[42]);
    gcrx<2, 1>(r, c[43]);
    gcrx<3, 2>(r, c[44]);
    PHASE_STORE(7, 6, 5, 4);
}
__device__ __forceinline__ void phB4(ull* st, const float2* c, int tid) {
    PHASE_LOAD(4, 3, 2, 1);
    gry<1>(r, c[32]); gry<2>(r, c[33]);
    gcrx<1, 0>(r, c[45]);
    gcrx<2, 1>(r, c[46]);
    gcrx<3, 2>(r, c[47]);
    PHASE_STORE(4, 3, 2, 1);
}

__device__ __forceinline__ void run_layer(ull* st, const float2* c, int tid) {
    phA1(st, c, tid); __syncthreads();
    phA2(st, c, tid); __syncthreads();
    phA3(st, c, tid); __syncthreads();
    phA4(st, c, tid); __syncthreads();
    phB1(st, c, tid); __syncthreads();
    phB2(st, c, tid); __syncthreads();
    phB3(st, c, tid); __syncthreads();
    phB4(st, c, tid); __syncthreads();
}

// ---------------------------------------------------------------------------
// Kernel 1 (merged prep): blocks [0, 5120): zero/init g_work.
//                         blocks [5120, 7168): param projection for bt.
// ---------------------------------------------------------------------------
#define INIT_BLKS ((DEGREE + 1) * BATCH * DIM / 256)   // 5120
__global__ void prep_kernel(const float* __restrict__ x,
                            const float* __restrict__ Wp,
                            const float* __restrict__ bp,
                            const float* __restrict__ qff) {
    if (blockIdx.x < INIT_BLKS) {
        uint32_t e = blockIdx.x * 256 + threadIdx.x;
        float2* flat = &g_work[0][0];
        uint32_t buf = e >> 18;
        uint32_t rem = e & 0x3FFFFu;
        float2 v = make_float2(0.f, 0.f);
        if (buf == 0 && (rem & (DIM - 1)) == 0) v.x = 1.f;
        flat[e] = v;
        return;
    }
    __shared__ float xr[FDIM];
    int bt = blockIdx.x - INIT_BLKS;   // 0..2047
    int r = threadIdx.x;               // 0..255 (only 0..95 produce)
    if (r < FDIM) xr[r] = x[bt * FDIM + r];
    __syncthreads();
    if (r < NROTS) {
        float acc = bp[r];
#pragma unroll
        for (int f = 0; f < FDIM; ++f) acc += xr[f] * Wp[r * FDIM + f];
        float sg = 1.0f / (1.0f + expf(-acc));
        float h = 3.14159265358979323846f * sg;   // theta/2 = pi * sigmoid
        float sv, cv; sincosf(h, &sv, &cv);
        g_cs[bt * NROTS + r] = make_float2(cv, sv);
        if (bt == 0 && r < QFFROTS) {
            float hq = 0.5f * qff[r];
            float sq, cq; sincosf(hq, &sq, &cq);
            g_csqff[r] = make_float2(cq, sq);
        }
    }
}

// ---------------------------------------------------------------------------
// Kernel 2: one polynomial degree. grid = 2048 (one CTA per (b,t)).
// ---------------------------------------------------------------------------
__global__ void __launch_bounds__(256, 4)
circuit_kernel(const ull* __restrict__ win, float2* __restrict__ wout,
               const float* __restrict__ mix_re, const float* __restrict__ mix_im) {
    extern __shared__ ull dsm[];
    ull* st = dsm;                            // DIM
    float2* cc = (float2*)(dsm + DIM);        // 96 coeffs + mix at [96]

    const int tid = threadIdx.x;
    const int b = blockIdx.x >> 5;
    const int t = blockIdx.x & 31;

    // load input state (64-bit, coalesced; sw touches only bits 0..3)
#pragma unroll
    for (int k = 0; k < 16; ++k) {
        int i = tid + 256 * k;
        st[sw((uint32_t)i)] = win[b * DIM + i];
    }
    if (tid < NROTS) cc[tid] = g_cs[(b * TSTEPS + t) * NROTS + tid];
    if (tid == NROTS) cc[NROTS] = make_float2(mix_re[t], mix_im[t]);
    __syncthreads();

    run_layer(st, cc, tid);               // layer 0 (8 phases)
    const float2* c1 = cc + 48;
    // layer 1: first 7 phases, last phase kept in registers
    phA1(st, c1, tid); __syncthreads();
    phA2(st, c1, tid); __syncthreads();
    phA3(st, c1, tid); __syncthreads();
    phA4(st, c1, tid); __syncthreads();
    phB1(st, c1, tid); __syncthreads();
    phB2(st, c1, tid); __syncthreads();
    phB3(st, c1, tid); __syncthreads();
    {   // phB4 without store: mix[t] * psi -> red.global directly
        PHASE_LOAD(4, 3, 2, 1);
        gry<1>(r, c1[32]); gry<2>(r, c1[33]);
        gcrx<1, 0>(r, c1[45]);
        gcrx<2, 1>(r, c1[46]);
        gcrx<3, 2>(r, c1[47]);
        float2 mx = cc[NROTS];
        const ull mr2 = dup2(mx.x);
        const ull mpm = pk2(-mx.y, mx.y);   // mul(mpm, swap(v)) = (-mi*vy, mi*vx)
#pragma unroll
        for (int j = 0; j < 16; ++j) {
            uint32_t i = pidx<4, 3, 2, 1>(base, j);
            ull v = f2fma(mr2, r[j], f2mul(mpm, swp(r[j])));
            red2(&wout[b * DIM + i], upk(v));
        }
    }
}

// ---------------------------------------------------------------------------
// Kernel 3: assemble acc, normalize, qff layer, Pauli expvals, output linear.
// grid = 64 (one CTA per batch), 256 threads.
// ---------------------------------------------------------------------------
__global__ void final_kernel(const float* __restrict__ poly,
                             const float* __restrict__ W_out,
                             const float* __restrict__ b_out,
                             float* __restrict__ out) {
    __shared__ ull st[DIM];
    __shared__ float red[37];            // [0..35] expvals, [36] sumsq
    const int tid = threadIdx.x;
    const int b = blockIdx.x;

    float p[DEGREE + 1];
#pragma unroll
    for (int d = 0; d <= DEGREE; ++d) p[d] = poly[d];
    float sabs = 0.f;
#pragma unroll
    for (int d = 0; d <= DEGREE; ++d) sabs += fabsf(p[d]);
    const float inv_s = 1.f / sabs;

    if (tid == 0) red[36] = 0.f;
    const ull* wflat = (const ull*)&g_work[0][0];
    float lsq = 0.f;
#pragma unroll
    for (int k = 0; k < 16; ++k) {
        int i = tid + 256 * k;
        ull v = 0ull;
#pragma unroll
        for (int d = 0; d <= DEGREE; ++d) {
            ull w = wflat[(size_t)d * (BATCH * DIM) + b * DIM + i];
            v = f2fma(dup2(p[d]), w, v);
        }
        v = f2mul(dup2(inv_s), v);
        st[sw((uint32_t)i)] = v;
        float2 vf = upk(v);
        lsq += vf.x * vf.x + vf.y * vf.y;
    }
#pragma unroll
    for (int o = 16; o > 0; o >>= 1) lsq += __shfl_xor_sync(0xffffffffu, lsq, o);
    if ((tid & 31) == 0) atomicAdd(&red[36], lsq);
    __syncthreads();

    const float f = 1.f / (sqrtf(red[36]) + 1e-9f);
    const ull f2 = dup2(f);
#pragma unroll
    for (int k = 0; k < 16; ++k) {
        int i = tid + 256 * k;
        uint32_t s_ = sw((uint32_t)i);
        st[s_] = f2mul(f2, st[s_]);
    }
    __syncthreads();

    run_layer(st, g_csqff, tid);     // qff: one sim14 layer

    if (tid < 36) red[tid] = 0.f;
    __syncthreads();

    float xx[NQ], yy[NQ], zz[NQ];
#pragma unroll
    for (int w = 0; w < NQ; ++w) { xx[w] = 0.f; yy[w] = 0.f; zz[w] = 0.f; }

#pragma unroll
    for (int k = 0; k < 16; ++k) {
        int i = tid + 256 * k;
        float2 a = upk(st[sw((uint32_t)i)]);
        float n2 = a.x * a.x + a.y * a.y;
#pragma unroll
        for (int w = 0; w < NQ; ++w) {
            int pbit = 11 - w;
            if (((i >> pbit) & 1) == 0) {
                float2 a1 = upk(st[sw((uint32_t)(i | (1 << pbit)))]);
                xx[w] += 2.f * (a.x * a1.x + a.y * a1.y);
                yy[w] += 2.f * (a.x * a1.y - a.y * a1.x);
                zz[w] += n2;
            } else {
                zz[w] -= n2;
            }
        }
    }
#pragma unroll
    for (int w = 0; w < NQ; ++w) {
        atomicAdd(&red[w], xx[w]);
        atomicAdd(&red[12 + w], yy[w]);
        atomicAdd(&red[24 + w], zz[w]);
    }
    __syncthreads();

    if (tid < ODIM) {
        float acc = b_out[tid];
#pragma unroll
        for (int j = 0; j < 36; ++j) acc += W_out[tid * 36 + j] * red[j];
        out[b * ODIM + tid] = acc;
    }
}

// ---------------------------------------------------------------------------
// Inputs (metadata order): x, W_proj, b_proj, poly_coeffs, mix_re, mix_im,
//                          qff_params, W_out, b_out.  Output: float32 [64,8].
// ---------------------------------------------------------------------------
extern "C" void kernel_launch(void* const* d_in, const int* in_sizes, int n_in,
                              void* d_out, int out_size) {
    (void)in_sizes; (void)n_in; (void)out_size;
    const float* x      = (const float*)d_in[0];
    const float* W_proj = (const float*)d_in[1];
    const float* b_proj = (const float*)d_in[2];
    const float* poly   = (const float*)d_in[3];
    const float* mix_re = (const float*)d_in[4];
    const float* mix_im = (const float*)d_in[5];
    const float* qff    = (const float*)d_in[6];
    const float* W_out  = (const float*)d_in[7];
    const float* b_out  = (const float*)d_in[8];
    float* out = (float*)d_out;

    cudaFuncSetAttribute(circuit_kernel,
                         cudaFuncAttributeMaxDynamicSharedMemorySize, CIRC_SMEM);

    prep_kernel<<<INIT_BLKS + BATCH * TSTEPS, 256>>>(x, W_proj, b_proj, qff);

    float2* w0;
    cudaGetSymbolAddress((void**)&w0, g_work);   // base of g_work
    float2* w1 = w0 + 1 * BATCH * DIM;
    float2* w2 = w0 + 2 * BATCH * DIM;
    float2* w3 = w0 + 3 * BATCH * DIM;
    float2* w4 = w0 + 4 * BATCH * DIM;

    circuit_kernel<<<NBLK_CIRC, 256, CIRC_SMEM>>>((const ull*)w0, w1, mix_re, mix_im);
    circuit_kernel<<<NBLK_CIRC, 256, CIRC_SMEM>>>((const ull*)w1, w2, mix_re, mix_im);
    circuit_kernel<<<NBLK_CIRC, 256, CIRC_SMEM>>>((const ull*)w2, w3, mix_re, mix_im);
    circuit_kernel<<<NBLK_CIRC, 256, CIRC_SMEM>>>((const ull*)w3, w4, mix_re, mix_im);

    final_kernel<<<BATCH, 256>>>(poly, W_out, b_out, out);
}